// round 9
// baseline (speedup 1.0000x reference)
#include <cuda_runtime.h>

#define T_STEPS 1000
#define B_TOT   256
#define FIN     39
#define H       100
#define G3      300
#define NCLS    20
#define GSTR    (B_TOT * G3)

typedef unsigned long long u64;

// 307 MB scratch for precomputed input gates gi[t][b][g]
// (includes b_ih for all gates, plus b_hh for r,z gates)
__device__ float g_gi[(size_t)T_STEPS * B_TOT * G3];

__device__ __forceinline__ u64 pk(float x, float y) {
    u64 r; asm("mov.b64 %0,{%1,%2};" : "=l"(r) : "f"(x), "f"(y)); return r;
}
__device__ __forceinline__ void fma2(u64 &d, u64 a, u64 b) {
    asm("fma.rn.f32x2 %0,%1,%2,%0;" : "+l"(d) : "l"(a), "l"(b));
}
__device__ __forceinline__ u64 add2(u64 a, u64 b) {
    u64 r; asm("add.rn.f32x2 %0,%1,%2;" : "=l"(r) : "l"(a), "l"(b)); return r;
}
__device__ __forceinline__ float hsum2(u64 a) {
    float x, y; asm("mov.b64 {%0,%1},%2;" : "=f"(x), "=f"(y) : "l"(a)); return x + y;
}
__device__ __forceinline__ void lds_v2u64(u64 &a, u64 &b, unsigned addr) {
    asm volatile("ld.shared.v2.u64 {%0,%1},[%2];" : "=l"(a), "=l"(b) : "r"(addr));
}
__device__ __forceinline__ void lds_u64(u64 &a, unsigned addr) {
    asm volatile("ld.shared.u64 %0,[%1];" : "=l"(a) : "r"(addr));
}
__device__ __forceinline__ float ex2f(float x) {
    float r; asm("ex2.approx.f32 %0, %1;" : "=f"(r) : "f"(x)); return r;
}
__device__ __forceinline__ float rcpf(float x) {
    float r; asm("rcp.approx.f32 %0, %1;" : "=f"(r) : "f"(x)); return r;
}
// sigmoid(x) = 1/(1+2^(-x*log2e)) : mul + ex2 + add + rcp (2 MUFU)
__device__ __forceinline__ float sigf(float x) {
    return rcpf(1.0f + ex2f(-1.4426950408889634f * x));
}
// tanh(x) = 2/(1+2^(-2x*log2e)) - 1
__device__ __forceinline__ float tanh_acc(float x) {
    return fmaf(2.0f, rcpf(1.0f + ex2f(-2.8853900817779268f * x)), -1.0f);
}

// ---------------------------------------------------------------------------
// Kernel 1: gi[t][b][g] = bias[g] + sum_k x[t][b][k] * W_ih[g][k]
// bias folds b_ih (all gates) + b_hh (r,z gates only — n's b_hh sits inside r*()).
// ---------------------------------------------------------------------------
#define K1_PAIRS 64
#define K1_TILE  32

__global__ void __launch_bounds__(320, 2) gi_precompute_kernel(
    const float* __restrict__ mfcc0, const float* __restrict__ mfcc1,
    const float* __restrict__ mfcc2,
    const float* __restrict__ W_ih, const float* __restrict__ b_ih,
    const float* __restrict__ b_hh)
{
    __shared__ __align__(16) float xt[2][K1_TILE][40];
    const int tid = threadIdx.x;
    const int g = (tid < G3) ? tid : (G3 - 1);

    u64 wih[20];
    {
        const float* w = W_ih + g * FIN;
        #pragma unroll
        for (int j = 0; j < 19; j++) wih[j] = pk(w[2 * j], w[2 * j + 1]);
        wih[19] = pk(w[38], 0.0f);
    }
    const float bias = b_ih[g] + ((g < 2 * H) ? b_hh[g] : 0.0f);
    const int p0 = blockIdx.x * K1_PAIRS;

    int fpair[4], fk[4];
    const float* fptr[4];
    bool fok[4];
    #pragma unroll
    for (int s = 0; s < 4; s++) {
        int idx = tid + s * 320;
        int pr = idx / 40, k = idx - pr * 40;
        fpair[s] = pr; fk[s] = k;
        fok[s] = (k < 39);
        const float* src = (k < 13) ? mfcc0 : (k < 26) ? mfcc1 : mfcc2;
        int f = (k < 13) ? k : (k < 26) ? (k - 13) : (k - 26);
        fptr[s] = src + (size_t)(p0 + pr) * 13 + f;
    }

    #pragma unroll
    for (int s = 0; s < 4; s++)
        xt[0][fpair[s]][fk[s]] = fok[s] ? __ldg(fptr[s]) : 0.0f;
    __syncthreads();

    const unsigned xB0 = (unsigned)__cvta_generic_to_shared(&xt[0][0][0]);

    for (int tile = 0; tile < K1_PAIRS / K1_TILE; tile++) {
        if (tile + 1 < K1_PAIRS / K1_TILE) {
            #pragma unroll
            for (int s = 0; s < 4; s++) {
                fptr[s] += K1_TILE * 13;
                xt[(tile + 1) & 1][fpair[s]][fk[s]] = fok[s] ? __ldg(fptr[s]) : 0.0f;
            }
        }
        const unsigned xB = xB0 + (tile & 1) * (K1_TILE * 40 * 4);
        const int pb = p0 + tile * K1_TILE;
        #pragma unroll 2
        for (int pair = 0; pair < K1_TILE; pair += 2) {
            u64 a0 = 0, a1 = 0, c0 = 0, c1 = 0;
            unsigned ad = xB + pair * 160;
            #pragma unroll
            for (int j = 0; j < 10; j++) {
                u64 p, q, p2, q2;
                lds_v2u64(p,  q,  ad + j * 16);
                lds_v2u64(p2, q2, ad + 160 + j * 16);
                fma2(a0, wih[2 * j],     p);
                fma2(a1, wih[2 * j + 1], q);
                fma2(c0, wih[2 * j],     p2);
                fma2(c1, wih[2 * j + 1], q2);
            }
            if (tid < G3) {
                g_gi[(size_t)(pb + pair) * G3 + g]     = hsum2(a0) + hsum2(a1) + bias;
                g_gi[(size_t)(pb + pair + 1) * G3 + g] = hsum2(c0) + hsum2(c1) + bias;
            }
        }
        __syncthreads();
    }
}

// ---------------------------------------------------------------------------
// Kernel 2: persistent recurrent GRU, batch-staggered software pipeline.
// 128 CTAs x 800 threads. thread = (h = tid>>3, ln = tid&7 = K-chunk of 14).
// Each STEP = 2 segments. Segment u: reduce+finalize batch u's partials
// (computed last segment) WHILE issuing LDS + 21 fma2 for the other batch.
// The reduce/sigmoid/tanh serial tail overlaps the other batch's fma stream.
// Reduction: parity-role butterfly, 7 SHFL (lane0: r,n; lane1: z; ship z).
// Single h buffer (reader/writer regions disjoint per segment); 1 bar/segment.
// SMEM slots: 80B stride -> 16B-aligned + conflict-free (banks {0,20,8,28,...}).
// ---------------------------------------------------------------------------
#define CH     14          // used floats per chunk
#define SLOT   80          // chunk slot bytes (20 floats)
#define HPB    640         // bytes per batch (8 slots)

__global__ void __launch_bounds__(800, 1) gru_rec_kernel(
    const float* __restrict__ len0,
    const float* __restrict__ W_hh, const float* __restrict__ b_hh,
    const float* __restrict__ W_out, const float* __restrict__ b_out,
    float* __restrict__ out)
{
    __shared__ __align__(16) float h_sh[2 * HPB / 4];   // single buffer: 2 batches
    __shared__ float feat_sh[2][2 * H];

    const int tid = threadIdx.x;
    const int h   = tid >> 3;          // 0..99
    const int ln  = tid & 7;           // K-chunk; lane0: r/n finalize, lane1: z
    const int b0  = blockIdx.x * 2;

    // zero h buffer (incl pad floats — pads never written again)
    for (int i = tid; i < 2 * HPB / 4; i += 800) h_sh[i] = 0.0f;

    // persistent W_hh chunk rows for 3 gates, zero-padded beyond k=100
    const int k0 = ln * CH;
    u64 w[3][7];
    #pragma unroll
    for (int i = 0; i < 3; i++) {
        const float* wr = W_hh + (h + i * H) * H;
        #pragma unroll
        for (int j = 0; j < 7; j++) {
            int k = k0 + 2 * j;
            float x0 = (k     < H) ? wr[k]     : 0.0f;
            float x1 = (k + 1 < H) ? wr[k + 1] : 0.0f;
            w[i][j] = pk(x0, x1);
        }
    }

    // gi pointers: lane0 reads r (+n at +nOff), lane1 reads z (+garbage n, unused)
    const bool gl = (ln < 2);
    const int  zo   = (ln == 1) ? H : 0;
    const int  nOff = 2 * H - zo;                     // gA + nOff = n entry
    const float* gA0 = g_gi + (size_t)b0 * G3 + zo + h;        // batch 0
    const float* gA1 = gA0 + G3;                               // batch 1
    float gvA0 = 0.0f, gvB0 = 0.0f, gvA1 = 0.0f, gvB1 = 0.0f;
    if (gl) {
        gvA0 = __ldg(gA0); gvB0 = __ldg(gA0 + nOff);
        gvA1 = __ldg(gA1); gvB1 = __ldg(gA1 + nOff);
    }
    const float bhn = b_hh[2 * H + h];

    // per-batch finalize state (valid on lane0 only)
    float hp0 = 0.0f, hp1 = 0.0f;
    float hs0 = 0.0f, hs1 = 0.0f;
    float hm0 = -1e30f, hm1 = -1e30f;

    // pipeline partials (batch0 @ t=0: h=0 -> all-zero partials)
    float pr = 0.0f, pz = 0.0f, pn = 0.0f;

    const unsigned base = (unsigned)__cvta_generic_to_shared(&h_sh[0]);
    const unsigned rd0 = base + (unsigned)(ln * SLOT);          // batch0 chunk
    const unsigned rd1 = rd0 + HPB;                             // batch1 chunk
    const unsigned wsl = (unsigned)((h / CH) * SLOT + (h % CH) * 4);
    const unsigned wr0 = base + wsl, wr1 = wr0 + HPB;

    __syncthreads();

    for (int t = 0; t < T_STEPS; t++) {
        // ================= segment u=0: reduce batch0(t), fma batch1(t) ======
        {
            // issue batch1 LDS early (consumed after the reduce chain)
            u64 q0, q1, q2, q3, q4, q5, q6;
            lds_v2u64(q0, q1, rd1);      lds_v2u64(q2, q3, rd1 + 16);
            lds_v2u64(q4, q5, rd1 + 32); lds_u64(q6, rd1 + 48);

            // parity-role butterfly over 8 chunks (7 SHFL)
            float o  = __shfl_xor_sync(0xFFFFFFFFu, (ln & 1) ? pr : pz, 1);
            float rz = ((ln & 1) ? pz : pr) + o;
            float nn = pn + __shfl_xor_sync(0xFFFFFFFFu, pn, 1);
            rz += __shfl_xor_sync(0xFFFFFFFFu, rz, 2);
            nn += __shfl_xor_sync(0xFFFFFFFFu, nn, 2);
            rz += __shfl_xor_sync(0xFFFFFFFFu, rz, 4);
            nn += __shfl_xor_sync(0xFFFFFFFFu, nn, 4);
            // lane0: rz=Sr, nn=Sn ; lane1: rz=Sz
            float sig = sigf(gvA0 + rz);                    // lane0: r, lane1: z
            float zx  = __shfl_xor_sync(0xFFFFFFFFu, sig, 1);
            float n   = tanh_acc(gvB0 + sig * (nn + bhn));
            float hn  = n + zx * (hp0 - n);
            hp0 = hn; hs0 += hn; hm0 = fmaxf(hm0, hn);
            if (ln == 0)
                asm volatile("st.shared.f32 [%0], %1;" :: "r"(wr0), "f"(hn));

            // prefetch gi batch0 (t+1); window = 2 segments
            if (gl && t + 1 < T_STEPS) {
                gA0 += GSTR;
                gvA0 = __ldg(gA0); gvB0 = __ldg(gA0 + nOff);
            }

            // batch1(t) partial dots: 3 gates x 2-deep accums
            u64 ra = 0, rb = 0, za = 0, zb = 0, na = 0, nb = 0;
            fma2(ra, w[0][0], q0); fma2(za, w[1][0], q0); fma2(na, w[2][0], q0);
            fma2(rb, w[0][1], q1); fma2(zb, w[1][1], q1); fma2(nb, w[2][1], q1);
            fma2(ra, w[0][2], q2); fma2(za, w[1][2], q2); fma2(na, w[2][2], q2);
            fma2(rb, w[0][3], q3); fma2(zb, w[1][3], q3); fma2(nb, w[2][3], q3);
            fma2(ra, w[0][4], q4); fma2(za, w[1][4], q4); fma2(na, w[2][4], q4);
            fma2(rb, w[0][5], q5); fma2(zb, w[1][5], q5); fma2(nb, w[2][5], q5);
            fma2(ra, w[0][6], q6); fma2(za, w[1][6], q6); fma2(na, w[2][6], q6);
            pr = hsum2(add2(ra, rb));
            pz = hsum2(add2(za, zb));
            pn = hsum2(add2(na, nb));
        }
        __syncthreads();

        // ================= segment u=1: reduce batch1(t), fma batch0(t+1) ====
        {
            u64 q0, q1, q2, q3, q4, q5, q6;
            lds_v2u64(q0, q1, rd0);      lds_v2u64(q2, q3, rd0 + 16);
            lds_v2u64(q4, q5, rd0 + 32); lds_u64(q6, rd0 + 48);

            float o  = __shfl_xor_sync(0xFFFFFFFFu, (ln & 1) ? pr : pz, 1);
            float rz = ((ln & 1) ? pz : pr) + o;
            float nn = pn + __shfl_xor_sync(0xFFFFFFFFu, pn, 1);
            rz += __shfl_xor_sync(0xFFFFFFFFu, rz, 2);
            nn += __shfl_xor_sync(0xFFFFFFFFu, nn, 2);
            rz += __shfl_xor_sync(0xFFFFFFFFu, rz, 4);
            nn += __shfl_xor_sync(0xFFFFFFFFu, nn, 4);
            float sig = sigf(gvA1 + rz);
            float zx  = __shfl_xor_sync(0xFFFFFFFFu, sig, 1);
            float n   = tanh_acc(gvB1 + sig * (nn + bhn));
            float hn  = n + zx * (hp1 - n);
            hp1 = hn; hs1 += hn; hm1 = fmaxf(hm1, hn);
            if (ln == 0)
                asm volatile("st.shared.f32 [%0], %1;" :: "r"(wr1), "f"(hn));

            if (gl && t + 1 < T_STEPS) {
                gA1 += GSTR;
                gvA1 = __ldg(gA1); gvB1 = __ldg(gA1 + nOff);
            }

            // batch0(t+1) partial dots (last iter: harmless, discarded)
            u64 ra = 0, rb = 0, za = 0, zb = 0, na = 0, nb = 0;
            fma2(ra, w[0][0], q0); fma2(za, w[1][0], q0); fma2(na, w[2][0], q0);
            fma2(rb, w[0][1], q1); fma2(zb, w[1][1], q1); fma2(nb, w[2][1], q1);
            fma2(ra, w[0][2], q2); fma2(za, w[1][2], q2); fma2(na, w[2][2], q2);
            fma2(rb, w[0][3], q3); fma2(zb, w[1][3], q3); fma2(nb, w[2][3], q3);
            fma2(ra, w[0][4], q4); fma2(za, w[1][4], q4); fma2(na, w[2][4], q4);
            fma2(rb, w[0][5], q5); fma2(zb, w[1][5], q5); fma2(nb, w[2][5], q5);
            fma2(ra, w[0][6], q6); fma2(za, w[1][6], q6); fma2(na, w[2][6], q6);
            pr = hsum2(add2(ra, rb));
            pz = hsum2(add2(za, zb));
            pn = hsum2(add2(na, nb));
        }
        __syncthreads();
    }

    // pooling features (lane0 holds both batches' pools)
    if (ln == 0) {
        float inv0 = 1.0f / len0[b0];
        float inv1 = 1.0f / len0[b0 + 1];
        feat_sh[0][h]     = hs0 * inv0;
        feat_sh[0][H + h] = hm0;
        feat_sh[1][h]     = hs1 * inv1;
        feat_sh[1][H + h] = hm1;
    }
    __syncthreads();

    // output linear: [2 x 20] = feat[2 x 200] @ W_out^T + b_out
    if (tid < 2 * NCLS) {
        int bb = tid / NCLS, cc = tid % NCLS;
        const float* wrp = W_out + cc * 2 * H;
        float acc = b_out[cc];
        #pragma unroll 4
        for (int j = 0; j < 2 * H; j++) acc += feat_sh[bb][j] * wrp[j];
        out[(b0 + bb) * NCLS + cc] = acc;
    }
}

extern "C" void kernel_launch(void* const* d_in, const int* in_sizes, int n_in,
                              void* d_out, int out_size)
{
    const float* mfcc0 = (const float*)d_in[0];
    const float* mfcc1 = (const float*)d_in[1];
    const float* mfcc2 = (const float*)d_in[2];
    const float* len0  = (const float*)d_in[3];
    const float* W_ih  = (const float*)d_in[4];
    const float* W_hh  = (const float*)d_in[5];
    const float* b_ih  = (const float*)d_in[6];
    const float* b_hh  = (const float*)d_in[7];
    const float* W_out = (const float*)d_in[8];
    const float* b_out = (const float*)d_in[9];
    float* out = (float*)d_out;

    gi_precompute_kernel<<<(T_STEPS * B_TOT) / K1_PAIRS, 320>>>(
        mfcc0, mfcc1, mfcc2, W_ih, b_ih, b_hh);
    gru_rec_kernel<<<B_TOT / 2, 800>>>(len0, W_hh, b_hh, W_out, b_out, out);
}